// round 8
// baseline (speedup 1.0000x reference)
#include <cuda_runtime.h>

typedef unsigned long long u64;

#define CB  2048
#define CT  512
#define CI  64
#define CH  32
#define CG  128

// Scratch: g_xg[((t*CB + b)*32 + j)*2 + {0,1}] = {(xg_i,xg_f),(xg_g,xg_o)} for unit j.
// One extra timestep slab so K2's t+1 prefetch never reads OOB.
__device__ u64 g_xg[(size_t)(CT + 1) * CB * 64];

__device__ __forceinline__ u64 ffma2(u64 a, u64 b, u64 c) {
    u64 d;
    asm("fma.rn.f32x2 %0, %1, %2, %3;" : "=l"(d) : "l"(a), "l"(b), "l"(c));
    return d;
}
__device__ __forceinline__ u64 pack2(float lo, float hi) {
    u64 d;
    asm("mov.b64 %0, {%1, %2};" : "=l"(d) : "f"(lo), "f"(hi));
    return d;
}
__device__ __forceinline__ float2 unpack2(u64 v) {
    float2 r;
    asm("mov.b64 {%0, %1}, %2;" : "=f"(r.x), "=f"(r.y) : "l"(v));
    return r;
}

// ---------------------------------------------------------------------------
// K1: input projection as ONE flattened GEMM over rows m = b*CT + t.
//   out_row(m) = x_row(m) @ W_ih^T + bias      [1M x 64] x [64 x 128]
// Block: 256 thr, 8 tiles of 128 rows, W staged once (dup'd u64), x staged
// single-buffered. xs uses an XOR swizzle on the row index (bits [4:2] by
// (k>>2)&7) -> staging STS is 2-way instead of 8-way bank conflicted, while
// compute-side 16B LDS alignment and f32x2 row-pairing are preserved.
// Thread tile: 2 j-cols x 4 gate-blocks x 8 rows (f32x2 over row pairs).
// ---------------------------------------------------------------------------
#define WTS2 130      // u64 stride for Wt2 rows
#define XTS  132      // float stride for xs rows (k index)
#define K1T  8        // row-tiles per block

extern __shared__ char sm1[];

__global__ __launch_bounds__(256, 2) void k1_inproj(
    const float* __restrict__ x, const float* __restrict__ Wih,
    const float* __restrict__ bih, const float* __restrict__ bhh)
{
    u64*   Wt2 = (u64*)sm1;                        // Wt2[k*WTS2 + g] = {w,w}
    float* xs  = (float*)(sm1 + 64 * WTS2 * 8);    // xs[k*XTS + swz(m,k)]
    const int tid = threadIdx.x;
    const size_t m0 = (size_t)blockIdx.x * (128 * K1T);

    // Stage W_ih duplicated (once per block)
    #pragma unroll
    for (int idx = tid; idx < CG * CI; idx += 256) {
        int g = idx >> 6, k = idx & 63;
        float w = Wih[idx];
        Wt2[k * WTS2 + g] = pack2(w, w);
    }

    const int tx = tid & 15, ty = tid >> 4;
    const int jj0 = tx * 2, r0 = ty * 8;
    const int mr = tid >> 4, kq = tid & 15;   // staging coords (row, float4-col)
    const int sw4 = 4 * (kq & 7);             // staging swizzle for this thread

    // Bias pairs
    u64 bd[2][4];
    #pragma unroll
    for (int q = 0; q < 2; q++)
        #pragma unroll
        for (int gb = 0; gb < 4; gb++) {
            int g = gb * 32 + jj0 + q;
            float bs = bih[g] + bhh[g];
            bd[q][gb] = pack2(bs, bs);
        }

    const float4* x4 = (const float4*)x;   // 16 float4 per row

    // Prologue: load tile 0
    float4 nxt[8];
    #pragma unroll
    for (int i = 0; i < 8; i++)
        nxt[i] = x4[(m0 + mr + i * 16) * 16 + kq];

    for (int tile = 0; tile < K1T; tile++) {
        const size_t mt = m0 + (size_t)tile * 128;

        __syncthreads();   // previous k-loop done with xs
        #pragma unroll
        for (int i = 0; i < 8; i++) {
            const int col = (mr + i * 16) ^ sw4;      // swizzled row index
            float* d = &xs[(4 * kq) * XTS + col];
            d[0 * XTS] = nxt[i].x;  d[1 * XTS] = nxt[i].y;
            d[2 * XTS] = nxt[i].z;  d[3 * XTS] = nxt[i].w;
        }
        __syncthreads();

        // Prefetch next tile (LDGs in flight under the k-loop)
        if (tile + 1 < K1T) {
            #pragma unroll
            for (int i = 0; i < 8; i++)
                nxt[i] = x4[(mt + 128 + mr + i * 16) * 16 + kq];
        }

        u64 acc[2][4][4];
        #pragma unroll
        for (int q = 0; q < 2; q++)
            #pragma unroll
            for (int gb = 0; gb < 4; gb++)
                #pragma unroll
                for (int p = 0; p < 4; p++) acc[q][gb][p] = bd[q][gb];

        #pragma unroll 4
        for (int k = 0; k < CI; k++) {
            const int sw = 4 * ((k >> 2) & 7);        // uniform per 4-group
            const ulonglong2 xa = *(const ulonglong2*)&xs[k * XTS + (r0 ^ sw)];
            const ulonglong2 xb = *(const ulonglong2*)&xs[k * XTS + ((r0 + 4) ^ sw)];
            u64 xp[4] = {xa.x, xa.y, xb.x, xb.y};
            const ulonglong2 w0 = *(const ulonglong2*)&Wt2[k * WTS2 +  0 + jj0];
            const ulonglong2 w1 = *(const ulonglong2*)&Wt2[k * WTS2 + 32 + jj0];
            const ulonglong2 w2 = *(const ulonglong2*)&Wt2[k * WTS2 + 64 + jj0];
            const ulonglong2 w3 = *(const ulonglong2*)&Wt2[k * WTS2 + 96 + jj0];
            #pragma unroll
            for (int p = 0; p < 4; p++) {
                acc[0][0][p] = ffma2(xp[p], w0.x, acc[0][0][p]);
                acc[0][1][p] = ffma2(xp[p], w1.x, acc[0][1][p]);
                acc[0][2][p] = ffma2(xp[p], w2.x, acc[0][2][p]);
                acc[0][3][p] = ffma2(xp[p], w3.x, acc[0][3][p]);
                acc[1][0][p] = ffma2(xp[p], w0.y, acc[1][0][p]);
                acc[1][1][p] = ffma2(xp[p], w1.y, acc[1][1][p]);
                acc[1][2][p] = ffma2(xp[p], w2.y, acc[1][2][p]);
                acc[1][3][p] = ffma2(xp[p], w3.y, acc[1][3][p]);
            }
        }

        // Store. Row pair (even m_e, odd m_e+1) = consecutive t, same b.
        #pragma unroll
        for (int p = 0; p < 4; p++) {
            const size_t m_e = mt + r0 + 2 * p;
            const int b = (int)(m_e >> 9);
            const int t = (int)(m_e & 511);
            #pragma unroll
            for (int q = 0; q < 2; q++) {
                float2 g0 = unpack2(acc[q][0][p]);
                float2 g1 = unpack2(acc[q][1][p]);
                float2 g2 = unpack2(acc[q][2][p]);
                float2 g3 = unpack2(acc[q][3][p]);
                u64* dst = g_xg + ((size_t)t * CB + b) * 64 + (jj0 + q) * 2;
                ulonglong2 ve, vo;
                ve.x = pack2(g0.x, g1.x);  ve.y = pack2(g2.x, g3.x);
                vo.x = pack2(g0.y, g1.y);  vo.y = pack2(g2.y, g3.y);
                *(ulonglong2*)dst = ve;                      // timestep t
                *(ulonglong2*)(dst + (size_t)CB * 64) = vo;  // timestep t+1
            }
        }
    }
}

// ---------------------------------------------------------------------------
// K2: recurrence. Each warp owns 2 batches; lane j = hidden unit j.
// W_hh register-resident as gate-pairs (64 u64, no smem weight traffic).
// h exchanged via per-warp smem, pre-duplicated: hs[w][k] = {<h0,h0>,<h1,h1>}
// -> per k: 1 broadcast LDS.128 + 4 FFMA2, zero packs, zero shuffles.
// fc fused at the end.
// ---------------------------------------------------------------------------
__device__ __forceinline__ float sigmf(float v) {
    return __fdividef(1.f, 1.f + __expf(-v));
}
__device__ __forceinline__ float tanhf_fast(float v) {
    return 1.f - __fdividef(2.f, 1.f + __expf(2.f * v));
}
__device__ __forceinline__ void lstm_cell(float gi, float gf, float gg, float go,
                                          float& c, float& h) {
    float iv = sigmf(gi);
    float fv = sigmf(gf);
    float gv = tanhf_fast(gg);
    float ov = sigmf(go);
    c = fv * c + iv * gv;
    h = ov * tanhf_fast(c);
}

#define K2W 4   // warps per block

__global__ __launch_bounds__(32 * K2W) void k2_rnn(
    const float* __restrict__ Whh, const float* __restrict__ wfc,
    const float* __restrict__ bfc, float* __restrict__ out)
{
    __shared__ ulonglong2 hs[K2W][CH];   // per-warp: {<h0,h0>,<h1,h1>} per unit

    const int tid = threadIdx.x;
    const int j   = tid & 31;
    const int w   = tid >> 5;
    const int b0  = (blockIdx.x * K2W + w) * 2;

    // Register-resident recurrent weights, gate-paired per unit j:
    // wif[k] = {W_hh[i_j][k], W_hh[f_j][k]},  wgo[k] = {W_hh[g_j][k], W_hh[o_j][k]}
    u64 wif[CH], wgo[CH];
    #pragma unroll
    for (int k = 0; k < CH; k++) {
        wif[k] = pack2(__ldg(&Whh[(0 * CH + j) * CH + k]),
                       __ldg(&Whh[(1 * CH + j) * CH + k]));
        wgo[k] = pack2(__ldg(&Whh[(2 * CH + j) * CH + k]),
                       __ldg(&Whh[(3 * CH + j) * CH + k]));
    }

    {
        ulonglong2 z;
        z.x = pack2(0.f, 0.f);
        z.y = pack2(0.f, 0.f);
        hs[w][j] = z;
    }
    float h0 = 0.f, h1 = 0.f, c0 = 0.f, c1 = 0.f;
    const float wfcv = wfc[j];
    __syncwarp();

    // xg pointers: ((t*CB + b0+bi)*32 + j)*2 u64
    const u64* xptr = g_xg + ((size_t)b0) * 64 + j * 2;
    const size_t TSTRIDE = (size_t)CB * 64;

    ulonglong2 xc0 = *(const ulonglong2*)(xptr);
    ulonglong2 xc1 = *(const ulonglong2*)(xptr + 64);
    xptr += TSTRIDE;

    for (int t = 0; t < CT; t++) {
        ulonglong2 xn0 = *(const ulonglong2*)(xptr);
        ulonglong2 xn1 = *(const ulonglong2*)(xptr + 64);
        xptr += TSTRIDE;

        u64 a0_if = xc0.x, a0_go = xc0.y;
        u64 a1_if = xc1.x, a1_go = xc1.y;

        #pragma unroll
        for (int k = 0; k < CH; k++) {
            const ulonglong2 hd = hs[w][k];   // broadcast: {<h0,h0>,<h1,h1>}
            a0_if = ffma2(hd.x, wif[k], a0_if);
            a0_go = ffma2(hd.x, wgo[k], a0_go);
            a1_if = ffma2(hd.y, wif[k], a1_if);
            a1_go = ffma2(hd.y, wgo[k], a1_go);
        }
        __syncwarp();   // all lanes done reading hs(t)

        float2 p0 = unpack2(a0_if);   // {i, f}
        float2 p1 = unpack2(a0_go);   // {g, o}
        lstm_cell(p0.x, p0.y, p1.x, p1.y, c0, h0);
        float2 q0 = unpack2(a1_if);
        float2 q1 = unpack2(a1_go);
        lstm_cell(q0.x, q0.y, q1.x, q1.y, c1, h1);

        {
            ulonglong2 v;
            v.x = pack2(h0, h0);
            v.y = pack2(h1, h1);
            hs[w][j] = v;
        }
        __syncwarp();   // hs(t+1) visible before next k-loop

        xc0 = xn0;  xc1 = xn1;
    }

    // Fused fc: out[b] = sum_j h[b][j] * W_fc[0][j] + b_fc
    float v0 = h0 * wfcv;
    float v1 = h1 * wfcv;
    #pragma unroll
    for (int off = 16; off > 0; off >>= 1) {
        v0 += __shfl_xor_sync(0xffffffffu, v0, off);
        v1 += __shfl_xor_sync(0xffffffffu, v1, off);
    }
    if (j == 0) {
        float bb = bfc[0];
        out[b0]     = v0 + bb;
        out[b0 + 1] = v1 + bb;
    }
}

// ---------------------------------------------------------------------------
extern "C" void kernel_launch(void* const* d_in, const int* in_sizes, int n_in,
                              void* d_out, int out_size)
{
    const float* x   = (const float*)d_in[0];
    const float* Wih = (const float*)d_in[1];
    const float* Whh = (const float*)d_in[2];
    const float* bih = (const float*)d_in[3];
    const float* bhh = (const float*)d_in[4];
    const float* Wfc = (const float*)d_in[5];
    const float* bfc = (const float*)d_in[6];
    float* out = (float*)d_out;

    const int smem1 = 64 * WTS2 * 8 + 64 * XTS * 4;  // 66560 + 33792 = 100352 B
    cudaFuncSetAttribute(k1_inproj, cudaFuncAttributeMaxDynamicSharedMemorySize, smem1);

    const int g1 = (CB * CT) / (128 * K1T);   // 1024 blocks
    k1_inproj<<<g1, 256, smem1>>>(x, Wih, bih, bhh);
    k2_rnn<<<CB / (2 * K2W), 32 * K2W>>>(Whh, Wfc, bfc, out);
}

// round 9
// speedup vs baseline: 1.0990x; 1.0990x over previous
#include <cuda_runtime.h>

typedef unsigned long long u64;

#define CB  2048
#define CT  512
#define CI  64
#define CH  32
#define CG  128

// Scratch: g_xg[((t*CB + b)*32 + j)*2 + {0,1}] = {(xg_i,xg_f),(xg_g,xg_o)} for unit j.
// One extra timestep slab so K2's t+1 prefetch never reads OOB.
__device__ u64 g_xg[(size_t)(CT + 1) * CB * 64];

__device__ __forceinline__ u64 ffma2(u64 a, u64 b, u64 c) {
    u64 d;
    asm("fma.rn.f32x2 %0, %1, %2, %3;" : "=l"(d) : "l"(a), "l"(b), "l"(c));
    return d;
}
__device__ __forceinline__ u64 addx2(u64 a, u64 b) {
    u64 d;
    asm("add.rn.f32x2 %0, %1, %2;" : "=l"(d) : "l"(a), "l"(b));
    return d;
}
__device__ __forceinline__ u64 pack2(float lo, float hi) {
    u64 d;
    asm("mov.b64 %0, {%1, %2};" : "=l"(d) : "f"(lo), "f"(hi));
    return d;
}
__device__ __forceinline__ float2 unpack2(u64 v) {
    float2 r;
    asm("mov.b64 {%0, %1}, %2;" : "=f"(r.x), "=f"(r.y) : "l"(v));
    return r;
}

// ---------------------------------------------------------------------------
// K1: input projection, flattened GEMM over rows m = b*CT + t.
// Block 256 thr, 8 tiles of 128 rows, double-buffered x staging (1 sync/tile).
// Thread: units jj = tx, tx+16 (q=0,1); gate-pairs pp0=(i,f), pp1=(g,o) in
// f32x2; 8 scalar rows. Weights: 4 dense LDS.64/k. x: 2 LDS.128/k + 8 packs.
// acc u64s are ALREADY in scratch format -> dense 16B-contiguous stores.
// ---------------------------------------------------------------------------
#define WTS 65        // u64 stride per k-row of weights (64 + 1 pad)
#define XTS 132       // float stride for xs rows (k index)
#define K1T 8         // row-tiles per block

extern __shared__ char sm1[];

__global__ __launch_bounds__(256, 2) void k1_inproj(
    const float* __restrict__ x, const float* __restrict__ Wih,
    const float* __restrict__ bih, const float* __restrict__ bhh)
{
    u64*   Wt  = (u64*)sm1;                        // Wt[k*WTS + cls*16 + tx]
    float* xs0 = (float*)(sm1 + 64 * WTS * 8);
    float* xs1 = xs0 + 64 * XTS;
    const int tid = threadIdx.x;
    const size_t m0 = (size_t)blockIdx.x * (128 * K1T);

    // Stage gate-paired weights: cls = q*2+pp, unit u = u0 + 16q.
    // Wt[k][cls*16+u0] = {W[u + pp*64][k], W[u+32 + pp*64][k]}
    #pragma unroll
    for (int idx = tid; idx < 64 * 64; idx += 256) {
        int k = idx >> 6, e = idx & 63;
        int cls = e >> 4, u0 = e & 15;
        int q = cls >> 1, pp = cls & 1;
        int u = u0 + q * 16;
        Wt[k * WTS + e] = pack2(Wih[(u + pp * 64) * 64 + k],
                                Wih[(u + 32 + pp * 64) * 64 + k]);
    }

    const int tx = tid & 15, ty = tid >> 4;
    const int r0 = ty * 8;
    const int mr = tid >> 4, kq = tid & 15;   // staging coords (row, float4-col)
    const int sw4 = 4 * (kq & 7);             // staging swizzle

    // Bias pairs: bd[q][pp] = {b[jj + pp*64], b[jj+32 + pp*64]}, jj = tx+16q
    u64 bd[2][2];
    #pragma unroll
    for (int q = 0; q < 2; q++)
        #pragma unroll
        for (int pp = 0; pp < 2; pp++) {
            int g = tx + 16 * q + pp * 64;
            bd[q][pp] = pack2(bih[g] + bhh[g], bih[g + 32] + bhh[g + 32]);
        }

    const float4* x4 = (const float4*)x;   // 16 float4 per row

    // Prologue: load + stage tile 0 into xs0
    float4 nxt[8];
    #pragma unroll
    for (int i = 0; i < 8; i++)
        nxt[i] = x4[(m0 + mr + i * 16) * 16 + kq];
    #pragma unroll
    for (int i = 0; i < 8; i++) {
        const int col = (mr + i * 16) ^ sw4;
        float* d = &xs0[(4 * kq) * XTS + col];
        d[0 * XTS] = nxt[i].x;  d[1 * XTS] = nxt[i].y;
        d[2 * XTS] = nxt[i].z;  d[3 * XTS] = nxt[i].w;
    }
    __syncthreads();

    for (int tile = 0; tile < K1T; tile++) {
        float* cur = (tile & 1) ? xs1 : xs0;
        float* alt = (tile & 1) ? xs0 : xs1;
        const size_t mt = m0 + (size_t)tile * 128;

        // Prefetch next tile (LDGs fly under the k-loop)
        if (tile + 1 < K1T) {
            #pragma unroll
            for (int i = 0; i < 8; i++)
                nxt[i] = x4[(mt + 128 + mr + i * 16) * 16 + kq];
        }

        u64 acc[2][2][8];
        #pragma unroll
        for (int q = 0; q < 2; q++)
            #pragma unroll
            for (int pp = 0; pp < 2; pp++)
                #pragma unroll
                for (int r = 0; r < 8; r++) acc[q][pp][r] = bd[q][pp];

        #pragma unroll 4
        for (int k = 0; k < CI; k++) {
            const int sw = 4 * ((k >> 2) & 7);
            const float4 xa = *(const float4*)&cur[k * XTS + (r0 ^ sw)];
            const float4 xb = *(const float4*)&cur[k * XTS + ((r0 + 4) ^ sw)];
            u64 xd[8] = {pack2(xa.x, xa.x), pack2(xa.y, xa.y),
                         pack2(xa.z, xa.z), pack2(xa.w, xa.w),
                         pack2(xb.x, xb.x), pack2(xb.y, xb.y),
                         pack2(xb.z, xb.z), pack2(xb.w, xb.w)};
            #pragma unroll
            for (int q = 0; q < 2; q++) {
                const u64 wif_ = Wt[k * WTS + q * 32 + tx];        // LDS.64 dense
                const u64 wgo_ = Wt[k * WTS + q * 32 + 16 + tx];   // LDS.64 dense
                #pragma unroll
                for (int r = 0; r < 8; r++) {
                    acc[q][0][r] = ffma2(xd[r], wif_, acc[q][0][r]);
                    acc[q][1][r] = ffma2(xd[r], wgo_, acc[q][1][r]);
                }
            }
        }

        // Stage next tile into alt buffer
        if (tile + 1 < K1T) {
            #pragma unroll
            for (int i = 0; i < 8; i++) {
                const int col = (mr + i * 16) ^ sw4;
                float* d = &alt[(4 * kq) * XTS + col];
                d[0 * XTS] = nxt[i].x;  d[1 * XTS] = nxt[i].y;
                d[2 * XTS] = nxt[i].z;  d[3 * XTS] = nxt[i].w;
            }
        }

        // Store: dst = g_xg + ((t*CB + b)*64) + jj*2, jj = tx + 16q.
        // b constant per tile (tiles never straddle a batch).
        {
            const int b = (int)(mt >> 9);
            const int tb = (int)(mt & 511) + r0;
            #pragma unroll
            for (int q = 0; q < 2; q++) {
                const int jj = tx + 16 * q;
                #pragma unroll
                for (int r = 0; r < 8; r++) {
                    u64* dst = g_xg + ((size_t)(tb + r) * CB + b) * 64 + jj * 2;
                    ulonglong2 v;
                    v.x = acc[q][0][r];   // {i, f}
                    v.y = acc[q][1][r];   // {g, o}
                    *(ulonglong2*)dst = v;
                }
            }
        }
        __syncthreads();
    }
}

// ---------------------------------------------------------------------------
// K2: recurrence, 2-warp cooperative k-split. Block = 2 warps / 2 batches.
// Warp w: k-half [16w, 16w+16), 64 weight regs, activates batch blk*2+w.
// Per k: 2 broadcast LDS.64 (h dup'd) + 4 FFMA2. Per t: partial exchange via
// smem (1 STS.128 + 1 LDS.128 + 2 add.f32x2), 2 block barriers. fc fused.
// ---------------------------------------------------------------------------
__device__ __forceinline__ float sigmf(float v) {
    return __fdividef(1.f, 1.f + __expf(-v));
}
__device__ __forceinline__ float tanhf_fast(float v) {
    return 1.f - __fdividef(2.f, 1.f + __expf(2.f * v));
}
__device__ __forceinline__ void lstm_cell(float gi, float gf, float gg, float go,
                                          float& c, float& h) {
    float iv = sigmf(gi);
    float fv = sigmf(gf);
    float gv = tanhf_fast(gg);
    float ov = sigmf(go);
    c = fv * c + iv * gv;
    h = ov * tanhf_fast(c);
}

__global__ __launch_bounds__(64) void k2_rnn(
    const float* __restrict__ Whh, const float* __restrict__ wfc,
    const float* __restrict__ bfc, float* __restrict__ out)
{
    __shared__ u64 hsd[2][CH];          // hsd[bi][k] = {h_bi[k], h_bi[k]}
    __shared__ ulonglong2 pex[2][CH];   // partial {if, go} exchange

    const int tid = threadIdx.x;
    const int j   = tid & 31;           // hidden unit
    const int w   = tid >> 5;           // warp: k-half and owned batch
    const int b   = blockIdx.x * 2 + w; // batch this warp activates
    const int kb  = w * 16;

    // Register weights for this warp's k-half, gate-paired per unit j
    u64 wif[16], wgo[16];
    #pragma unroll
    for (int kk = 0; kk < 16; kk++) {
        int k = kb + kk;
        wif[kk] = pack2(__ldg(&Whh[j * CH + k]),          // i row j
                        __ldg(&Whh[(32 + j) * CH + k]));  // f
        wgo[kk] = pack2(__ldg(&Whh[(64 + j) * CH + k]),   // g
                        __ldg(&Whh[(96 + j) * CH + k]));  // o
    }

    hsd[w][j] = 0ull;
    float h = 0.f, c = 0.f;
    const float wfcv = wfc[j];
    __syncthreads();

    const u64* hown = hsd[w];        // h of the batch this warp activates
    const u64* hoth = hsd[1 - w];

    const u64* xptr = g_xg + ((size_t)b) * 64 + j * 2;
    const size_t TSTRIDE = (size_t)CB * 64;

    ulonglong2 xc = *(const ulonglong2*)xptr;
    xptr += TSTRIDE;

    for (int t = 0; t < CT; t++) {
        ulonglong2 xn = *(const ulonglong2*)xptr;
        xptr += TSTRIDE;

        // Partial sums over this warp's k-half: own batch starts from xg,
        // other batch's partial starts at 0 (its xg lives in the other warp).
        u64 so_if = xc.x, so_go = xc.y;
        u64 sx_if = 0ull, sx_go = 0ull;

        #pragma unroll
        for (int kk = 0; kk < 16; kk++) {
            const u64 ho = hown[kb + kk];   // broadcast LDS.64
            const u64 hx = hoth[kb + kk];   // broadcast LDS.64
            so_if = ffma2(ho, wif[kk], so_if);
            so_go = ffma2(ho, wgo[kk], so_go);
            sx_if = ffma2(hx, wif[kk], sx_if);
            sx_go = ffma2(hx, wgo[kk], sx_go);
        }

        // Exchange: my partial for the OTHER batch
        {
            ulonglong2 px;
            px.x = sx_if;  px.y = sx_go;
            pex[w][j] = px;
        }
        __syncthreads();
        {
            const ulonglong2 pp = pex[1 - w][j];   // partner's partial for my batch
            u64 t_if = addx2(so_if, pp.x);
            u64 t_go = addx2(so_go, pp.y);
            float2 gif = unpack2(t_if);   // {i_pre, f_pre}
            float2 ggo = unpack2(t_go);   // {g_pre, o_pre}
            lstm_cell(gif.x, gif.y, ggo.x, ggo.y, c, h);
        }
        hsd[w][j] = pack2(h, h);
        __syncthreads();

        xc = xn;
    }

    // Fused fc for this warp's batch
    float v = h * wfcv;
    #pragma unroll
    for (int off = 16; off > 0; off >>= 1)
        v += __shfl_xor_sync(0xffffffffu, v, off);
    if (j == 0) out[b] = v + bfc[0];
}

// ---------------------------------------------------------------------------
extern "C" void kernel_launch(void* const* d_in, const int* in_sizes, int n_in,
                              void* d_out, int out_size)
{
    const float* x   = (const float*)d_in[0];
    const float* Wih = (const float*)d_in[1];
    const float* Whh = (const float*)d_in[2];
    const float* bih = (const float*)d_in[3];
    const float* bhh = (const float*)d_in[4];
    const float* Wfc = (const float*)d_in[5];
    const float* bfc = (const float*)d_in[6];
    float* out = (float*)d_out;

    const int smem1 = 64 * WTS * 8 + 2 * 64 * XTS * 4;  // 33280 + 67584 = 100864 B
    cudaFuncSetAttribute(k1_inproj, cudaFuncAttributeMaxDynamicSharedMemorySize, smem1);

    const int g1 = (CB * CT) / (128 * K1T);   // 1024 blocks
    k1_inproj<<<g1, 256, smem1>>>(x, Wih, bih, bhh);
    k2_rnn<<<CB / 2, 64>>>(Whh, Wfc, bfc, out);
}